// round 11
// baseline (speedup 1.0000x reference)
#include <cuda_runtime.h>
#include <cstdint>

// CompressKV: y[b,m,h,d] = (sum_k x[b, m*16+k, h, d]*w[k] + sum_k pe[k,d]*w[k]) / 32
// x (4,16384,8,128) f32, w (32) f32, pe (32,128) f32, y (4,1023,8,128) f32.
//
// FINAL (converged at the roofline; measured best: bench 47.84us, kernel
// 45.70us @ 6.2 TB/s). TMA bulk 3-stage x 32 KB ring, 2 windows per CTA
// (2048 CTAs), 2 CTAs/SM. Rolling A/B register accumulators: each 8-token
// group is read from smem once and feeds two overlapping windows (k=16..31
// of the older, k=0..15 of the newer). Mandatory traffic 285 MB at the
// chip's measured ~6.24 TB/s DRAM-path ceiling -> ~45.7us bound, which this
// kernel achieves.

#define CB 4
#define CN 16384
#define CH 8
#define CD 128
#define CK 32
#define CM 1023
#define WCHUNK 2                    // windows per CTA
#define NCHUNKS 512                 // ceil(1023/2)
#define GTOK 8                      // tokens per group
#define GROUP_BYTES (GTOK * CH * CD * 4)   // 32768
#define NGROUPS (2 * WCHUNK + 2)    // 6
#define STAGES 3
#define LANES 256                   // float4 lanes per token row
#define SMEM_DATA_OFF 1024
#define SMEM_TOTAL (SMEM_DATA_OFF + STAGES * GROUP_BYTES)   // 99328
#define MAX_T 2047                  // last valid 8-token group index

__device__ __forceinline__ uint32_t smem_u32(const void* p) {
    uint32_t a;
    asm("{ .reg .u64 t; cvta.to.shared.u64 t, %1; cvt.u32.u64 %0, t; }"
        : "=r"(a) : "l"(p));
    return a;
}

__device__ __forceinline__ void mbar_init(uint32_t mb, uint32_t cnt) {
    asm volatile("mbarrier.init.shared.b64 [%0], %1;" :: "r"(mb), "r"(cnt) : "memory");
}
__device__ __forceinline__ void mbar_expect_tx(uint32_t mb, uint32_t bytes) {
    asm volatile("mbarrier.arrive.expect_tx.shared.b64 _, [%0], %1;"
                 :: "r"(mb), "r"(bytes) : "memory");
}
__device__ __forceinline__ void mbar_wait(uint32_t mb, uint32_t parity) {
    asm volatile(
        "{\n\t"
        ".reg .pred P;\n\t"
        "WL_%=:\n\t"
        "mbarrier.try_wait.parity.acquire.cta.shared::cta.b64 P, [%0], %1, 0x989680;\n\t"
        "@P bra.uni WD_%=;\n\t"
        "bra.uni WL_%=;\n\t"
        "WD_%=:\n\t"
        "}"
        :: "r"(mb), "r"(parity) : "memory");
}
__device__ __forceinline__ void bulk_ld(uint32_t dst, const void* src, uint32_t mb) {
    asm volatile("cp.async.bulk.shared::cta.global.mbarrier::complete_tx::bytes "
                 "[%0], [%1], %2, [%3];"
                 :: "r"(dst), "l"(src), "n"(GROUP_BYTES), "r"(mb) : "memory");
}

__global__ __launch_bounds__(256, 2)
void compresskv_kernel(const float* __restrict__ x,
                       const float* __restrict__ w,
                       const float4* __restrict__ pe,
                       float4*      __restrict__ y)
{
    extern __shared__ char smem[];
    const uint32_t sbase = smem_u32(smem);
    const int tid = threadIdx.x;
    const int m0  = blockIdx.x * WCHUNK;
    const int b   = blockIdx.y;
    const int t0  = 2 * m0;                  // first global 8-token group

    if (tid == 0) {
#pragma unroll
        for (int s = 0; s < STAGES; ++s) mbar_init(sbase + 8u * s, 1);
    }
    __syncthreads();

    const char* xb = (const char*)x + (size_t)b * CN * (CH * CD * 4);

    // prologue: fill the ring
    if (tid == 0) {
#pragma unroll
        for (int j = 0; j < STAGES; ++j) {
            if (t0 + j <= MAX_T) {
                mbar_expect_tx(sbase + 8u * j, GROUP_BYTES);
                bulk_ld(sbase + SMEM_DATA_OFF + (uint32_t)j * GROUP_BYTES,
                        xb + (size_t)(t0 + j) * GROUP_BYTES, sbase + 8u * j);
            }
        }
    }

    // weights + bias (registers; pe is 16 KB, L2 resident)
    float wk[CK];
#pragma unroll
    for (int k = 0; k < CK; ++k) wk[k] = __ldg(&w[k]);

    float4 bias; bias.x = bias.y = bias.z = bias.w = 0.f;
#pragma unroll
    for (int k = 0; k < CK; ++k) {
        float4 p = __ldg(&pe[k * (CD / 4) + (tid & 31)]);
        bias.x = fmaf(wk[k], p.x, bias.x);
        bias.y = fmaf(wk[k], p.y, bias.y);
        bias.z = fmaf(wk[k], p.z, bias.z);
        bias.w = fmaf(wk[k], p.w, bias.w);
    }

    float4* yb = y + (size_t)b * CM * LANES + tid;

    float aAx = 0.f, aAy = 0.f, aAz = 0.f, aAw = 0.f;   // older window
    float aBx = 0.f, aBy = 0.f, aBz = 0.f, aBw = 0.f;   // newer window

#pragma unroll
    for (int j = 0; j < NGROUPS; ++j) {
        if (t0 + j <= MAX_T) {                           // uniform per block
            const int st = j % STAGES;
            mbar_wait(sbase + 8u * st, (j / STAGES) & 1);

            const float4* sp =
                (const float4*)(smem + SMEM_DATA_OFF + (size_t)st * GROUP_BYTES) + tid;
            const int koffB = 8 * (j & 1);               // compile-time
            const int koffA = 16 + 8 * (j & 1);
#pragma unroll
            for (int r = 0; r < GTOK; ++r) {
                float4 v = sp[r * LANES];
                if (j >= 2) {                            // older window is ours
                    aAx = fmaf(wk[koffA + r], v.x, aAx);
                    aAy = fmaf(wk[koffA + r], v.y, aAy);
                    aAz = fmaf(wk[koffA + r], v.z, aAz);
                    aAw = fmaf(wk[koffA + r], v.w, aAw);
                }
                if (j <= 2 * WCHUNK - 1) {               // newer window is ours
                    aBx = fmaf(wk[koffB + r], v.x, aBx);
                    aBy = fmaf(wk[koffB + r], v.y, aBy);
                    aBz = fmaf(wk[koffB + r], v.z, aBz);
                    aBw = fmaf(wk[koffB + r], v.w, aBw);
                }
            }
            __syncthreads();                             // stage st free
            if (tid == 0 && j + STAGES < NGROUPS && t0 + j + STAGES <= MAX_T) {
                mbar_expect_tx(sbase + 8u * st, GROUP_BYTES);
                bulk_ld(sbase + SMEM_DATA_OFF + (uint32_t)st * GROUP_BYTES,
                        xb + (size_t)(t0 + j + STAGES) * GROUP_BYTES, sbase + 8u * st);
            }

            if (j & 1) {                                 // window transition
                if (j >= 3) {
                    const int wdx = m0 + (j - 3) / 2;    // complete window
                    if (wdx <= CM - 1) {
                        float4 o;
                        o.x = (aAx + bias.x) * 0.03125f;
                        o.y = (aAy + bias.y) * 0.03125f;
                        o.z = (aAz + bias.z) * 0.03125f;
                        o.w = (aAw + bias.w) * 0.03125f;
                        yb[(size_t)wdx * LANES] = o;
                    }
                }
                aAx = aBx; aAy = aBy; aAz = aBz; aAw = aBw;
                aBx = 0.f; aBy = 0.f; aBz = 0.f; aBw = 0.f;
            }
        }
    }
}

extern "C" void kernel_launch(void* const* d_in, const int* in_sizes, int n_in,
                              void* d_out, int out_size)
{
    const float*  x  = (const float*) d_in[0];
    const float*  w  = (const float*) d_in[1];
    const float4* pe = (const float4*)d_in[2];
    float4*       y  = (float4*)d_out;

    static bool attr_set = false;
    if (!attr_set) {
        cudaFuncSetAttribute(compresskv_kernel,
                             cudaFuncAttributeMaxDynamicSharedMemorySize, SMEM_TOTAL);
        attr_set = true;
    }

    dim3 grid(NCHUNKS, CB);                  // (512, 4) = 2048 CTAs
    dim3 block(256);
    compresskv_kernel<<<grid, block, SMEM_TOTAL>>>(x, w, pe, y);
}

// round 12
// speedup vs baseline: 1.0120x; 1.0120x over previous
#include <cuda_runtime.h>
#include <cstdint>

// CompressKV: y[b,m,h,d] = (sum_k x[b, m*16+k, h, d]*w[k] + sum_k pe[k,d]*w[k]) / 32
// x (4,16384,8,128) f32, w (32) f32, pe (32,128) f32, y (4,1023,8,128) f32.
//
// FINAL — converged at the measured roofline (best bench 47.84us, kernel
// 45.7-46.7us @ 6.1-6.2 TB/s over three reproductions). TMA bulk 3-stage x
// 32 KB ring, 2 windows per CTA (2048 CTAs), 2 CTAs/SM. Rolling A/B register
// accumulators: each 8-token group is read from smem once and feeds two
// overlapping windows (k=16..31 of the older, k=0..15 of the newer).
// Mandatory traffic 285 MB at the chip's measured ~6.2 TB/s DRAM-path
// ceiling for this read/write mix -> ~45.7us bound, achieved. Six orthogonal
// structural levers (R3-R9) all left bandwidth invariant; R9 showed that
// perturbing the 2-CTA/SM timing breaks the L2 boundary-group dedup.

#define CB 4
#define CN 16384
#define CH 8
#define CD 128
#define CK 32
#define CM 1023
#define WCHUNK 2                    // windows per CTA
#define NCHUNKS 512                 // ceil(1023/2)
#define GTOK 8                      // tokens per group
#define GROUP_BYTES (GTOK * CH * CD * 4)   // 32768
#define NGROUPS (2 * WCHUNK + 2)    // 6
#define STAGES 3
#define LANES 256                   // float4 lanes per token row
#define SMEM_DATA_OFF 1024
#define SMEM_TOTAL (SMEM_DATA_OFF + STAGES * GROUP_BYTES)   // 99328
#define MAX_T 2047                  // last valid 8-token group index

__device__ __forceinline__ uint32_t smem_u32(const void* p) {
    uint32_t a;
    asm("{ .reg .u64 t; cvta.to.shared.u64 t, %1; cvt.u32.u64 %0, t; }"
        : "=r"(a) : "l"(p));
    return a;
}

__device__ __forceinline__ void mbar_init(uint32_t mb, uint32_t cnt) {
    asm volatile("mbarrier.init.shared.b64 [%0], %1;" :: "r"(mb), "r"(cnt) : "memory");
}
__device__ __forceinline__ void mbar_expect_tx(uint32_t mb, uint32_t bytes) {
    asm volatile("mbarrier.arrive.expect_tx.shared.b64 _, [%0], %1;"
                 :: "r"(mb), "r"(bytes) : "memory");
}
__device__ __forceinline__ void mbar_wait(uint32_t mb, uint32_t parity) {
    asm volatile(
        "{\n\t"
        ".reg .pred P;\n\t"
        "WL_%=:\n\t"
        "mbarrier.try_wait.parity.acquire.cta.shared::cta.b64 P, [%0], %1, 0x989680;\n\t"
        "@P bra.uni WD_%=;\n\t"
        "bra.uni WL_%=;\n\t"
        "WD_%=:\n\t"
        "}"
        :: "r"(mb), "r"(parity) : "memory");
}
__device__ __forceinline__ void bulk_ld(uint32_t dst, const void* src, uint32_t mb) {
    asm volatile("cp.async.bulk.shared::cta.global.mbarrier::complete_tx::bytes "
                 "[%0], [%1], %2, [%3];"
                 :: "r"(dst), "l"(src), "n"(GROUP_BYTES), "r"(mb) : "memory");
}

__global__ __launch_bounds__(256, 2)
void compresskv_kernel(const float* __restrict__ x,
                       const float* __restrict__ w,
                       const float4* __restrict__ pe,
                       float4*      __restrict__ y)
{
    extern __shared__ char smem[];
    const uint32_t sbase = smem_u32(smem);
    const int tid = threadIdx.x;
    const int m0  = blockIdx.x * WCHUNK;
    const int b   = blockIdx.y;
    const int t0  = 2 * m0;                  // first global 8-token group

    if (tid == 0) {
#pragma unroll
        for (int s = 0; s < STAGES; ++s) mbar_init(sbase + 8u * s, 1);
    }
    __syncthreads();

    const char* xb = (const char*)x + (size_t)b * CN * (CH * CD * 4);

    // prologue: fill the ring
    if (tid == 0) {
#pragma unroll
        for (int j = 0; j < STAGES; ++j) {
            if (t0 + j <= MAX_T) {
                mbar_expect_tx(sbase + 8u * j, GROUP_BYTES);
                bulk_ld(sbase + SMEM_DATA_OFF + (uint32_t)j * GROUP_BYTES,
                        xb + (size_t)(t0 + j) * GROUP_BYTES, sbase + 8u * j);
            }
        }
    }

    // weights + bias (registers; pe is 16 KB, L2 resident) — overlapped with
    // the prologue TMA loads.
    float wk[CK];
#pragma unroll
    for (int k = 0; k < CK; ++k) wk[k] = __ldg(&w[k]);

    float4 bias; bias.x = bias.y = bias.z = bias.w = 0.f;
#pragma unroll
    for (int k = 0; k < CK; ++k) {
        float4 p = __ldg(&pe[k * (CD / 4) + (tid & 31)]);
        bias.x = fmaf(wk[k], p.x, bias.x);
        bias.y = fmaf(wk[k], p.y, bias.y);
        bias.z = fmaf(wk[k], p.z, bias.z);
        bias.w = fmaf(wk[k], p.w, bias.w);
    }

    float4* yb = y + (size_t)b * CM * LANES + tid;

    float aAx = 0.f, aAy = 0.f, aAz = 0.f, aAw = 0.f;   // older window
    float aBx = 0.f, aBy = 0.f, aBz = 0.f, aBw = 0.f;   // newer window

#pragma unroll
    for (int j = 0; j < NGROUPS; ++j) {
        if (t0 + j <= MAX_T) {                           // uniform per block
            const int st = j % STAGES;
            mbar_wait(sbase + 8u * st, (j / STAGES) & 1);

            const float4* sp =
                (const float4*)(smem + SMEM_DATA_OFF + (size_t)st * GROUP_BYTES) + tid;
            const int koffB = 8 * (j & 1);               // compile-time
            const int koffA = 16 + 8 * (j & 1);
#pragma unroll
            for (int r = 0; r < GTOK; ++r) {
                float4 v = sp[r * LANES];
                if (j >= 2) {                            // older window is ours
                    aAx = fmaf(wk[koffA + r], v.x, aAx);
                    aAy = fmaf(wk[koffA + r], v.y, aAy);
                    aAz = fmaf(wk[koffA + r], v.z, aAz);
                    aAw = fmaf(wk[koffA + r], v.w, aAw);
                }
                if (j <= 2 * WCHUNK - 1) {               // newer window is ours
                    aBx = fmaf(wk[koffB + r], v.x, aBx);
                    aBy = fmaf(wk[koffB + r], v.y, aBy);
                    aBz = fmaf(wk[koffB + r], v.z, aBz);
                    aBw = fmaf(wk[koffB + r], v.w, aBw);
                }
            }
            __syncthreads();                             // stage st free
            if (tid == 0 && j + STAGES < NGROUPS && t0 + j + STAGES <= MAX_T) {
                mbar_expect_tx(sbase + 8u * st, GROUP_BYTES);
                bulk_ld(sbase + SMEM_DATA_OFF + (uint32_t)st * GROUP_BYTES,
                        xb + (size_t)(t0 + j + STAGES) * GROUP_BYTES, sbase + 8u * st);
            }

            if (j & 1) {                                 // window transition
                if (j >= 3) {
                    const int wdx = m0 + (j - 3) / 2;    // complete window
                    if (wdx <= CM - 1) {
                        float4 o;
                        o.x = (aAx + bias.x) * 0.03125f;
                        o.y = (aAy + bias.y) * 0.03125f;
                        o.z = (aAz + bias.z) * 0.03125f;
                        o.w = (aAw + bias.w) * 0.03125f;
                        yb[(size_t)wdx * LANES] = o;
                    }
                }
                aAx = aBx; aAy = aBy; aAz = aBz; aAw = aBw;
                aBx = 0.f; aBy = 0.f; aBz = 0.f; aBw = 0.f;
            }
        }
    }
}

extern "C" void kernel_launch(void* const* d_in, const int* in_sizes, int n_in,
                              void* d_out, int out_size)
{
    const float*  x  = (const float*) d_in[0];
    const float*  w  = (const float*) d_in[1];
    const float4* pe = (const float4*)d_in[2];
    float4*       y  = (float4*)d_out;

    static bool attr_set = false;
    if (!attr_set) {
        cudaFuncSetAttribute(compresskv_kernel,
                             cudaFuncAttributeMaxDynamicSharedMemorySize, SMEM_TOTAL);
        attr_set = true;
    }

    dim3 grid(NCHUNKS, CB);                  // (512, 4) = 2048 CTAs
    dim3 block(256);
    compresskv_kernel<<<grid, block, SMEM_TOTAL>>>(x, w, pe, y);
}

// round 13
// speedup vs baseline: 1.0175x; 1.0054x over previous
#include <cuda_runtime.h>
#include <cstdint>

// CompressKV: y[b,m,h,d] = (sum_k x[b, m*16+k, h, d]*w[k] + sum_k pe[k,d]*w[k]) / 32
// x (4,16384,8,128) f32, w (32) f32, pe (32,128) f32, y (4,1023,8,128) f32.
//
// R13 = R7 ring (3 x 32 KB, WCHUNK=2, 2048 CTAs, 2 CTA/SM) with the consumer
// __syncthreads replaced by per-stage empty mbarriers: each thread arrives on
// empty[st] after reading the stage; tid0 alone waits and issues the refill
// while other warps run ahead. Removes the block-wide rendezvous from the
// refill critical path.

#define CB 4
#define CN 16384
#define CH 8
#define CD 128
#define CK 32
#define CM 1023
#define WCHUNK 2                    // windows per CTA
#define NCHUNKS 512                 // ceil(1023/2)
#define GTOK 8                      // tokens per group
#define GROUP_BYTES (GTOK * CH * CD * 4)   // 32768
#define NGROUPS (2 * WCHUNK + 2)    // 6
#define STAGES 3
#define LANES 256                   // float4 lanes per token row
#define SMEM_DATA_OFF 1024
#define SMEM_TOTAL (SMEM_DATA_OFF + STAGES * GROUP_BYTES)   // 99328
#define MAX_T 2047                  // last valid 8-token group index

__device__ __forceinline__ uint32_t smem_u32(const void* p) {
    uint32_t a;
    asm("{ .reg .u64 t; cvta.to.shared.u64 t, %1; cvt.u32.u64 %0, t; }"
        : "=r"(a) : "l"(p));
    return a;
}

__device__ __forceinline__ void mbar_init(uint32_t mb, uint32_t cnt) {
    asm volatile("mbarrier.init.shared.b64 [%0], %1;" :: "r"(mb), "r"(cnt) : "memory");
}
__device__ __forceinline__ void mbar_expect_tx(uint32_t mb, uint32_t bytes) {
    asm volatile("mbarrier.arrive.expect_tx.shared.b64 _, [%0], %1;"
                 :: "r"(mb), "r"(bytes) : "memory");
}
__device__ __forceinline__ void mbar_arrive(uint32_t mb) {
    asm volatile("mbarrier.arrive.shared.b64 _, [%0];" :: "r"(mb) : "memory");
}
__device__ __forceinline__ void mbar_wait(uint32_t mb, uint32_t parity) {
    asm volatile(
        "{\n\t"
        ".reg .pred P;\n\t"
        "WL_%=:\n\t"
        "mbarrier.try_wait.parity.acquire.cta.shared::cta.b64 P, [%0], %1, 0x989680;\n\t"
        "@P bra.uni WD_%=;\n\t"
        "bra.uni WL_%=;\n\t"
        "WD_%=:\n\t"
        "}"
        :: "r"(mb), "r"(parity) : "memory");
}
__device__ __forceinline__ void bulk_ld(uint32_t dst, const void* src, uint32_t mb) {
    asm volatile("cp.async.bulk.shared::cta.global.mbarrier::complete_tx::bytes "
                 "[%0], [%1], %2, [%3];"
                 :: "r"(dst), "l"(src), "n"(GROUP_BYTES), "r"(mb) : "memory");
}

// interleaved barrier layout: full[s] at 16*s, empty[s] at 16*s + 8
#define FULL_BAR(s)  (sbase + 16u * (s))
#define EMPTY_BAR(s) (sbase + 16u * (s) + 8u)

__global__ __launch_bounds__(256, 2)
void compresskv_kernel(const float* __restrict__ x,
                       const float* __restrict__ w,
                       const float4* __restrict__ pe,
                       float4*      __restrict__ y)
{
    extern __shared__ char smem[];
    const uint32_t sbase = smem_u32(smem);
    const int tid = threadIdx.x;
    const int m0  = blockIdx.x * WCHUNK;
    const int b   = blockIdx.y;
    const int t0  = 2 * m0;                  // first global 8-token group

    if (tid == 0) {
#pragma unroll
        for (int s = 0; s < STAGES; ++s) {
            mbar_init(FULL_BAR(s), 1);       // tx-based completion
            mbar_init(EMPTY_BAR(s), 256);    // all threads arrive after reading
        }
    }
    __syncthreads();

    const char* xb = (const char*)x + (size_t)b * CN * (CH * CD * 4);

    // prologue: fill the ring
    if (tid == 0) {
#pragma unroll
        for (int j = 0; j < STAGES; ++j) {
            if (t0 + j <= MAX_T) {
                mbar_expect_tx(FULL_BAR(j), GROUP_BYTES);
                bulk_ld(sbase + SMEM_DATA_OFF + (uint32_t)j * GROUP_BYTES,
                        xb + (size_t)(t0 + j) * GROUP_BYTES, FULL_BAR(j));
            }
        }
    }

    // weights + bias (registers; pe is 16 KB, L2 resident) — overlapped with
    // the prologue TMA loads.
    float wk[CK];
#pragma unroll
    for (int k = 0; k < CK; ++k) wk[k] = __ldg(&w[k]);

    float4 bias; bias.x = bias.y = bias.z = bias.w = 0.f;
#pragma unroll
    for (int k = 0; k < CK; ++k) {
        float4 p = __ldg(&pe[k * (CD / 4) + (tid & 31)]);
        bias.x = fmaf(wk[k], p.x, bias.x);
        bias.y = fmaf(wk[k], p.y, bias.y);
        bias.z = fmaf(wk[k], p.z, bias.z);
        bias.w = fmaf(wk[k], p.w, bias.w);
    }

    float4* yb = y + (size_t)b * CM * LANES + tid;

    float aAx = 0.f, aAy = 0.f, aAz = 0.f, aAw = 0.f;   // older window
    float aBx = 0.f, aBy = 0.f, aBz = 0.f, aBw = 0.f;   // newer window

#pragma unroll
    for (int j = 0; j < NGROUPS; ++j) {
        if (t0 + j <= MAX_T) {                           // uniform per block
            const int st = j % STAGES;
            const uint32_t par = (uint32_t)((j / STAGES) & 1);
            mbar_wait(FULL_BAR(st), par);

            const float4* sp =
                (const float4*)(smem + SMEM_DATA_OFF + (size_t)st * GROUP_BYTES) + tid;
            const int koffB = 8 * (j & 1);               // compile-time
            const int koffA = 16 + 8 * (j & 1);
#pragma unroll
            for (int r = 0; r < GTOK; ++r) {
                float4 v = sp[r * LANES];
                if (j >= 2) {                            // older window is ours
                    aAx = fmaf(wk[koffA + r], v.x, aAx);
                    aAy = fmaf(wk[koffA + r], v.y, aAy);
                    aAz = fmaf(wk[koffA + r], v.z, aAz);
                    aAw = fmaf(wk[koffA + r], v.w, aAw);
                }
                if (j <= 2 * WCHUNK - 1) {               // newer window is ours
                    aBx = fmaf(wk[koffB + r], v.x, aBx);
                    aBy = fmaf(wk[koffB + r], v.y, aBy);
                    aBz = fmaf(wk[koffB + r], v.z, aBz);
                    aBw = fmaf(wk[koffB + r], v.w, aBw);
                }
            }

            // done reading stage st for this cycle
            if (j + STAGES < NGROUPS && t0 + j + STAGES <= MAX_T) {
                mbar_arrive(EMPTY_BAR(st));
                if (tid == 0) {                          // refill without block barrier
                    mbar_wait(EMPTY_BAR(st), par);
                    mbar_expect_tx(FULL_BAR(st), GROUP_BYTES);
                    bulk_ld(sbase + SMEM_DATA_OFF + (uint32_t)st * GROUP_BYTES,
                            xb + (size_t)(t0 + j + STAGES) * GROUP_BYTES, FULL_BAR(st));
                }
            }

            if (j & 1) {                                 // window transition
                if (j >= 3) {
                    const int wdx = m0 + (j - 3) / 2;    // complete window
                    if (wdx <= CM - 1) {
                        float4 o;
                        o.x = (aAx + bias.x) * 0.03125f;
                        o.y = (aAy + bias.y) * 0.03125f;
                        o.z = (aAz + bias.z) * 0.03125f;
                        o.w = (aAw + bias.w) * 0.03125f;
                        yb[(size_t)wdx * LANES] = o;
                    }
                }
                aAx = aBx; aAy = aBy; aAz = aBz; aAw = aBw;
                aBx = 0.f; aBy = 0.f; aBz = 0.f; aBw = 0.f;
            }
        }
    }
}

extern "C" void kernel_launch(void* const* d_in, const int* in_sizes, int n_in,
                              void* d_out, int out_size)
{
    const float*  x  = (const float*) d_in[0];
    const float*  w  = (const float*) d_in[1];
    const float4* pe = (const float4*)d_in[2];
    float4*       y  = (float4*)d_out;

    static bool attr_set = false;
    if (!attr_set) {
        cudaFuncSetAttribute(compresskv_kernel,
                             cudaFuncAttributeMaxDynamicSharedMemorySize, SMEM_TOTAL);
        attr_set = true;
    }

    dim3 grid(NCHUNKS, CB);                  // (512, 4) = 2048 CTAs
    dim3 block(256);
    compresskv_kernel<<<grid, block, SMEM_TOTAL>>>(x, w, pe, y);
}